// round 3
// baseline (speedup 1.0000x reference)
#include <cuda_runtime.h>
#include <math.h>

// RoIPool (max) — features (2,256,50,76) f32, rois (128,5) f32 -> out (128,256,7,7) f32
// Emulates the XLA-lowered JAX reference bit-for-bit:
//   x1,y1,x2,y2 = int(rint(roi * 0.0625))          (exact mul by 2^-4, half-even round)
//   extent = max(hi-lo+1, 1)
//   bin_sz = extent * fp32(1/7)                    <-- XLA rewrites  x / 7.0  into
//                                                      x * reciprocal-constant (1 IEEE mul)
//   start_p = floor(fp32_mul(p, bin_sz)) + lo ; end_p = ceil(fp32_mul(p+1, bin_sz)) + lo
//   clip to [0, size]; out = rectangle max; empty rectangle -> 0.

#define C_     256
#define H_     50
#define W_     76
#define PH_    7
#define PW_    7
#define NROIS_ 128
#define SCALE_ 0.0625f
// fp32 nearest to 1/7 (0x3E124925)
#define RECIP7_ 0.14285714924335479736328125f

__global__ void roipool_kernel(const float* __restrict__ feat,
                               const float* __restrict__ rois,
                               float* __restrict__ out)
{
    const int roi = blockIdx.y;
    const int t   = blockIdx.x * blockDim.x + threadIdx.x;   // 0 .. 12543 (=256*49), exact

    const float* r = rois + roi * 5;
    const int b  = (int)r[0];
    const int x1 = (int)rintf(__fmul_rn(r[1], SCALE_));
    const int y1 = (int)rintf(__fmul_rn(r[2], SCALE_));
    const int x2 = (int)rintf(__fmul_rn(r[3], SCALE_));
    const int y2 = (int)rintf(__fmul_rn(r[4], SCALE_));

    const int c  = t / (PH_ * PW_);
    const int s  = t - c * (PH_ * PW_);
    const int ph = s / PW_;
    const int pw = s - ph * PW_;

    // bin_sz via reciprocal multiply (XLA division-by-constant lowering)
    const float ext_h = (float)max(y2 - y1 + 1, 1);
    const float ext_w = (float)max(x2 - x1 + 1, 1);
    const float bh = __fmul_rn(ext_h, RECIP7_);
    const float bw = __fmul_rn(ext_w, RECIP7_);

    int hstart = (int)floorf(__fmul_rn((float)ph,       bh)) + y1;
    int hend   = (int)ceilf (__fmul_rn((float)(ph + 1), bh)) + y1;
    int wstart = (int)floorf(__fmul_rn((float)pw,       bw)) + x1;
    int wend   = (int)ceilf (__fmul_rn((float)(pw + 1), bw)) + x1;

    hstart = min(max(hstart, 0), H_);
    hend   = min(max(hend,   0), H_);
    wstart = min(max(wstart, 0), W_);
    wend   = min(max(wend,   0), W_);

    const float* plane = feat + ((size_t)b * C_ + c) * (H_ * W_);

    float m = -3.402823466e+38f;   // -FLT_MAX sentinel
    for (int h = hstart; h < hend; ++h) {
        const float* row = plane + h * W_;
        for (int w = wstart; w < wend; ++w) {
            m = fmaxf(m, __ldg(row + w));
        }
    }
    if (hend <= hstart || wend <= wstart) m = 0.0f;   // empty bin -> 0

    out[(size_t)roi * (C_ * PH_ * PW_) + t] = m;
}

extern "C" void kernel_launch(void* const* d_in, const int* in_sizes, int n_in,
                              void* d_out, int out_size)
{
    // Autodetect input order by element count (rois = 640 elems, features = 1,945,600).
    const float* feat;
    const float* rois;
    if (in_sizes[0] == NROIS_ * 5) {
        rois = (const float*)d_in[0];
        feat = (const float*)d_in[1];
    } else {
        feat = (const float*)d_in[0];
        rois = (const float*)d_in[1];
    }
    float* out = (float*)d_out;

    dim3 block(256);
    dim3 grid((C_ * PH_ * PW_) / 256, NROIS_);   // 49 x 128 blocks, exact coverage
    roipool_kernel<<<grid, block>>>(feat, rois, out);
}

// round 4
// speedup vs baseline: 1.0992x; 1.0992x over previous
#include <cuda_runtime.h>
#include <math.h>

// RoIPool (max) — features (2,256,50,76) f32, rois (128,5) f32 -> out (128,256,7,7) f32
// Bin arithmetic matches the XLA-lowered JAX reference bit-for-bit (incl. x/7 lowered
// to x * fp32(1/7)). Hot path: fully unrolled predicated 5x5 gather (box sides <= 316px
// -> extent <= ~21 cells -> bin_sz <= 3 -> bin rectangle <= 5x5), generic fallback for
// larger bins keeps it seed-robust.

#define C_     256
#define H_     50
#define W_     76
#define PH_    7
#define PW_    7
#define NROIS_ 128
#define SCALE_ 0.0625f
// fp32 nearest to 1/7 (0x3E124925)
#define RECIP7_ 0.14285714924335479736328125f
#define MAXBIN_ 5

__global__ void roipool_kernel(const float* __restrict__ feat,
                               const float* __restrict__ rois,
                               float* __restrict__ out)
{
    const int roi = blockIdx.y;
    const int t   = blockIdx.x * blockDim.x + threadIdx.x;   // 0 .. 12543 (=256*49)

    const float* r = rois + roi * 5;
    const int b  = (int)r[0];
    const int x1 = (int)rintf(__fmul_rn(r[1], SCALE_));
    const int y1 = (int)rintf(__fmul_rn(r[2], SCALE_));
    const int x2 = (int)rintf(__fmul_rn(r[3], SCALE_));
    const int y2 = (int)rintf(__fmul_rn(r[4], SCALE_));

    const int c  = t / (PH_ * PW_);
    const int s  = t - c * (PH_ * PW_);
    const int ph = s / PW_;
    const int pw = s - ph * PW_;

    // bin_sz via reciprocal multiply (XLA division-by-constant lowering)
    const float ext_h = (float)max(y2 - y1 + 1, 1);
    const float ext_w = (float)max(x2 - x1 + 1, 1);
    const float bh = __fmul_rn(ext_h, RECIP7_);
    const float bw = __fmul_rn(ext_w, RECIP7_);

    int hstart = (int)floorf(__fmul_rn((float)ph,       bh)) + y1;
    int hend   = (int)ceilf (__fmul_rn((float)(ph + 1), bh)) + y1;
    int wstart = (int)floorf(__fmul_rn((float)pw,       bw)) + x1;
    int wend   = (int)ceilf (__fmul_rn((float)(pw + 1), bw)) + x1;

    hstart = min(max(hstart, 0), H_);
    hend   = min(max(hend,   0), H_);
    wstart = min(max(wstart, 0), W_);
    wend   = min(max(wend,   0), W_);

    const int nh = hend - hstart;
    const int nw = wend - wstart;

    const float* plane = feat + ((size_t)b * C_ + c) * (H_ * W_);
    const float* p0    = plane + hstart * W_ + wstart;

    float m = -3.402823466e+38f;   // -FLT_MAX sentinel

    if (nh <= MAXBIN_ && nw <= MAXBIN_) {
        // Hot path: 25 predicated LDGs with constant offsets -> high MLP,
        // zero loop-control overhead. Predicated-off loads issue no wavefronts.
        #pragma unroll
        for (int i = 0; i < MAXBIN_; ++i) {
            #pragma unroll
            for (int j = 0; j < MAXBIN_; ++j) {
                if (i < nh && j < nw)
                    m = fmaxf(m, __ldg(p0 + i * W_ + j));
            }
        }
    } else {
        // Seed-robust fallback (not expected to execute with this input dist).
        for (int i = 0; i < nh; ++i)
            for (int j = 0; j < nw; ++j)
                m = fmaxf(m, __ldg(p0 + i * W_ + j));
    }

    if (nh <= 0 || nw <= 0) m = 0.0f;   // empty bin -> 0

    out[(size_t)roi * (C_ * PH_ * PW_) + t] = m;
}

extern "C" void kernel_launch(void* const* d_in, const int* in_sizes, int n_in,
                              void* d_out, int out_size)
{
    // Autodetect input order by element count (rois = 640 elems, features = 1,945,600).
    const float* feat;
    const float* rois;
    if (in_sizes[0] == NROIS_ * 5) {
        rois = (const float*)d_in[0];
        feat = (const float*)d_in[1];
    } else {
        feat = (const float*)d_in[0];
        rois = (const float*)d_in[1];
    }
    float* out = (float*)d_out;

    dim3 block(256);
    dim3 grid((C_ * PH_ * PW_) / 256, NROIS_);   // 49 x 128 blocks, exact coverage
    roipool_kernel<<<grid, block>>>(feat, rois, out);
}

// round 5
// speedup vs baseline: 1.3058x; 1.1880x over previous
#include <cuda_runtime.h>
#include <math.h>

// RoIPool (max) — features (2,256,50,76) f32, rois (128,5) f32 -> out (128,256,7,7) f32
// Bin arithmetic matches the XLA-lowered JAX reference bit-for-bit (x/7 lowered to
// x * fp32(1/7)). Hot path: per-roi UNIFORM tier dispatch on bin-size bound
// (n <= ceil(bin_sz)+1, bin_sz <= 3 for this input dist) -> templated NHxNW
// predicated gather, no warp divergence (one roi per block). Generic fallback
// keeps it seed-robust.

#define C_     256
#define H_     50
#define W_     76
#define PH_    7
#define PW_    7
#define NROIS_ 128
#define SCALE_ 0.0625f
// fp32 nearest to 1/7 (0x3E124925)
#define RECIP7_ 0.14285714924335479736328125f

template<int NH, int NW>
__device__ __forceinline__ float pool_tile(const float* __restrict__ p0,
                                           int nh, int nw)
{
    float m = -3.402823466e+38f;   // -FLT_MAX
    #pragma unroll
    for (int i = 0; i < NH; ++i) {
        #pragma unroll
        for (int j = 0; j < NW; ++j) {
            if (i < nh && j < nw)
                m = fmaxf(m, __ldg(p0 + i * W_ + j));
        }
    }
    return m;
}

__global__ void roipool_kernel(const float* __restrict__ feat,
                               const float* __restrict__ rois,
                               float* __restrict__ out)
{
    const int roi = blockIdx.y;
    const int t   = blockIdx.x * blockDim.x + threadIdx.x;   // 0 .. 12543 (=256*49)

    const float* r = rois + roi * 5;
    const int b  = (int)r[0];
    const int x1 = (int)rintf(__fmul_rn(r[1], SCALE_));
    const int y1 = (int)rintf(__fmul_rn(r[2], SCALE_));
    const int x2 = (int)rintf(__fmul_rn(r[3], SCALE_));
    const int y2 = (int)rintf(__fmul_rn(r[4], SCALE_));

    const int c  = t / (PH_ * PW_);
    const int s  = t - c * (PH_ * PW_);
    const int ph = s / PW_;
    const int pw = s - ph * PW_;

    // bin_sz via reciprocal multiply (XLA division-by-constant lowering)
    const float ext_h = (float)max(y2 - y1 + 1, 1);
    const float ext_w = (float)max(x2 - x1 + 1, 1);
    const float bh = __fmul_rn(ext_h, RECIP7_);
    const float bw = __fmul_rn(ext_w, RECIP7_);

    int hstart = (int)floorf(__fmul_rn((float)ph,       bh)) + y1;
    int hend   = (int)ceilf (__fmul_rn((float)(ph + 1), bh)) + y1;
    int wstart = (int)floorf(__fmul_rn((float)pw,       bw)) + x1;
    int wend   = (int)ceilf (__fmul_rn((float)(pw + 1), bw)) + x1;

    hstart = min(max(hstart, 0), H_);
    hend   = min(max(hend,   0), H_);
    wstart = min(max(wstart, 0), W_);
    wend   = min(max(wend,   0), W_);

    const int nh = hend - hstart;
    const int nw = wend - wstart;

    const float* p0 = feat + ((size_t)b * C_ + c) * (H_ * W_) + hstart * W_ + wstart;

    // Per-roi uniform tier: nh <= ceil(bh)+1, nw <= ceil(bw)+1.
    // bh,bw are identical for all threads of the block (one roi per block),
    // so this 2-level dispatch has no warp divergence.
    const int th = (bh <= 1.0f) ? 2 : (bh <= 2.0f) ? 3 : (bh <= 3.0f) ? 4 : 0;
    const int tw = (bw <= 1.0f) ? 2 : (bw <= 2.0f) ? 3 : (bw <= 3.0f) ? 4 : 0;

    float m;
    if (th && tw) {
        if (th == 2) {
            m = (tw == 2) ? pool_tile<2,2>(p0, nh, nw)
              : (tw == 3) ? pool_tile<2,3>(p0, nh, nw)
                          : pool_tile<2,4>(p0, nh, nw);
        } else if (th == 3) {
            m = (tw == 2) ? pool_tile<3,2>(p0, nh, nw)
              : (tw == 3) ? pool_tile<3,3>(p0, nh, nw)
                          : pool_tile<3,4>(p0, nh, nw);
        } else {
            m = (tw == 2) ? pool_tile<4,2>(p0, nh, nw)
              : (tw == 3) ? pool_tile<4,3>(p0, nh, nw)
                          : pool_tile<4,4>(p0, nh, nw);
        }
    } else {
        // Seed-robust generic fallback (bin_sz > 3 not expected with this dist).
        m = -3.402823466e+38f;
        for (int i = 0; i < nh; ++i)
            for (int j = 0; j < nw; ++j)
                m = fmaxf(m, __ldg(p0 + i * W_ + j));
    }

    if (nh <= 0 || nw <= 0) m = 0.0f;   // empty bin -> 0

    out[(size_t)roi * (C_ * PH_ * PW_) + t] = m;
}

extern "C" void kernel_launch(void* const* d_in, const int* in_sizes, int n_in,
                              void* d_out, int out_size)
{
    // Autodetect input order by element count (rois = 640 elems, features = 1,945,600).
    const float* feat;
    const float* rois;
    if (in_sizes[0] == NROIS_ * 5) {
        rois = (const float*)d_in[0];
        feat = (const float*)d_in[1];
    } else {
        feat = (const float*)d_in[0];
        rois = (const float*)d_in[1];
    }
    float* out = (float*)d_out;

    dim3 block(256);
    dim3 grid((C_ * PH_ * PW_) / 256, NROIS_);   // 49 x 128 blocks, exact coverage
    roipool_kernel<<<grid, block>>>(feat, rois, out);
}